// round 2
// baseline (speedup 1.0000x reference)
#include <cuda_runtime.h>
#include <cstddef>

// Problem constants
#define B_   256
#define S_   256
#define D_   1024
#define P_   512
#define SH   254            // S-2 head positions
#define NROWS (B_*SH)       // 65024
#define EPS_ 1e-7f

// Scratch (allocation-free rule: __device__ globals)
__device__ float g_bias[B_*P_];      // prep_proj + child_proj, per (b,p)
__device__ float g_scores[NROWS];    // pre-softmax scores
__device__ int   g_mask_mode;        // 0=int32, 1=float32, 2=bytes

__device__ __forceinline__ float fast_tanh(float x) {
    float y;
    asm("tanh.approx.f32 %0, %1;" : "=f"(y) : "f"(x));
    return y;
}

// ---------------------------------------------------------------------------
// Kernel 0: probe mask dtype. Safe: reads only first 65536 bytes (= smallest
// possible mask buffer: 65536 bool bytes). Deterministic.
// ---------------------------------------------------------------------------
__global__ void __launch_bounds__(256) mask_probe_kernel(const unsigned int* __restrict__ m)
{
    __shared__ int s01, sf;
    if (threadIdx.x == 0) { s01 = 1; sf = 1; }
    __syncthreads();
    // 16384 words, 256 threads x 64
    bool ok01 = true, okf = true;
    #pragma unroll 4
    for (int it = 0; it < 64; it++) {
        unsigned int v = m[threadIdx.x + it * 256];
        if (v > 1u) ok01 = false;
        if (v != 0u && v != 0x3F800000u) okf = false;
    }
    if (!ok01) atomicAnd(&s01, 0);
    if (!okf)  atomicAnd(&sf, 0);
    __syncthreads();
    if (threadIdx.x == 0)
        g_mask_mode = s01 ? 0 : (sf ? 1 : 2);
}

// ---------------------------------------------------------------------------
// Kernel 1: bias[b][p] = prep_enc[b]·proj_prep[:,p] + child_enc[b]·proj_child[:,p]
// grid (P/128=4, B/4=64), block 128. Stages 4 prep + 4 child rows in SMEM.
// ---------------------------------------------------------------------------
__global__ void __launch_bounds__(128) bias_kernel(
    const float* __restrict__ x,
    const float* __restrict__ wp,
    const float* __restrict__ wc)
{
    __shared__ float sP[4][D_];   // 16KB
    __shared__ float sC[4][D_];   // 16KB
    const int tid = threadIdx.x;
    const int b0  = blockIdx.y * 4;

    #pragma unroll
    for (int it = 0; it < 16; it++) {
        int idx  = tid + it * 128;        // float4 index in [8][256]
        int row  = idx >> 8;              // 0..7
        int col4 = idx & 255;
        int bb   = b0 + (row >> 1);
        int which = row & 1;              // 0 = prep (s=254), 1 = child (s=255)
        const float* src = x + ((size_t)bb * S_ + (S_ - 2) + which) * D_;
        float4 v = *(const float4*)(src + col4 * 4);
        float* dst = which ? &sC[row >> 1][0] : &sP[row >> 1][0];
        *(float4*)(dst + col4 * 4) = v;
    }
    __syncthreads();

    const int p = blockIdx.x * 128 + tid;
    float acc[4] = {0.f, 0.f, 0.f, 0.f};
    #pragma unroll 4
    for (int d = 0; d < D_; d++) {
        float a = wp[(size_t)d * P_ + p];
        float c = wc[(size_t)d * P_ + p];
        #pragma unroll
        for (int j = 0; j < 4; j++)
            acc[j] += sP[j][d] * a + sC[j][d] * c;
    }
    #pragma unroll
    for (int j = 0; j < 4; j++)
        g_bias[(size_t)(b0 + j) * P_ + p] = acc[j];
}

// ---------------------------------------------------------------------------
// Kernel 2: fused main pipeline (see round 0 notes).
// ---------------------------------------------------------------------------
#define TM 32
#define BK 16
#define MAIN_SMEM_FLOATS (TM*P_ + BK*P_ + TM*BK)   // comp + Ws + As = 25088
#define MAIN_SMEM_BYTES  (MAIN_SMEM_FLOATS * 4)    // 100352 B -> 2 CTAs/SM

__device__ __forceinline__ void load_w_chunk(float* Ws, const float* Wsrc, int tid) {
    const float4* src = (const float4*)Wsrc;   // 16x512 floats = 2048 float4
    float4* dst = (float4*)Ws;
    #pragma unroll
    for (int it = 0; it < 8; it++)
        dst[tid + it * 256] = src[tid + it * 256];
}

__global__ void __launch_bounds__(256, 2) main_kernel(
    const float* __restrict__ x,
    const float* __restrict__ w1,      // proj_head [D][P]
    const float* __restrict__ hid,     // [2][P][P]
    const float* __restrict__ scorer)  // [P]
{
    extern __shared__ float smem[];
    float* comp = smem;                // [TM][P]
    float* Ws   = smem + TM * P_;      // [BK][P]
    float* As   = Ws + BK * P_;        // [TM][BK]

    const int tid = threadIdx.x;
    const int tn  = tid & 31;          // lane
    const int tm  = tid >> 5;          // warp id = row group
    const int R0  = blockIdx.x * TM;

    int rb[4];
    #pragma unroll
    for (int i = 0; i < 4; i++) {
        int r = R0 + tm * 4 + i;
        rb[i] = r / SH;
    }

    const int mA = tid >> 3;
    int rA = R0 + mA;
    int bA = rA / SH;
    int sA = rA - bA * SH;
    const float* xrow = x + ((size_t)bA * S_ + sA) * D_;
    const int kkA = (tid & 7) * 2;

    float acc[64];

    // ---- init acc with bias ----
    #pragma unroll
    for (int i = 0; i < 4; i++) {
        const float* bb = g_bias + (size_t)rb[i] * P_;
        #pragma unroll
        for (int q = 0; q < 4; q++) {
            float4 v = *(const float4*)(bb + q * 128 + tn * 4);
            acc[i*16 + q*4 + 0] = v.x;
            acc[i*16 + q*4 + 1] = v.y;
            acc[i*16 + q*4 + 2] = v.z;
            acc[i*16 + q*4 + 3] = v.w;
        }
    }

    // ---- stage 1: + x @ proj_head, K = 1024 ----
    for (int k0 = 0; k0 < D_; k0 += BK) {
        __syncthreads();
        *(float2*)(&As[mA * BK + kkA]) = *(const float2*)(xrow + k0 + kkA);
        load_w_chunk(Ws, w1 + (size_t)k0 * P_, tid);
        __syncthreads();
        #pragma unroll
        for (int k = 0; k < BK; k++) {
            float a0 = As[(tm*4 + 0) * BK + k];
            float a1 = As[(tm*4 + 1) * BK + k];
            float a2 = As[(tm*4 + 2) * BK + k];
            float a3 = As[(tm*4 + 3) * BK + k];
            const float* wr = Ws + k * P_ + tn * 4;
            #pragma unroll
            for (int q = 0; q < 4; q++) {
                float4 bv = *(const float4*)(wr + q * 128);
                acc[ 0 + q*4 + 0] += a0 * bv.x; acc[ 0 + q*4 + 1] += a0 * bv.y;
                acc[ 0 + q*4 + 2] += a0 * bv.z; acc[ 0 + q*4 + 3] += a0 * bv.w;
                acc[16 + q*4 + 0] += a1 * bv.x; acc[16 + q*4 + 1] += a1 * bv.y;
                acc[16 + q*4 + 2] += a1 * bv.z; acc[16 + q*4 + 3] += a1 * bv.w;
                acc[32 + q*4 + 0] += a2 * bv.x; acc[32 + q*4 + 1] += a2 * bv.y;
                acc[32 + q*4 + 2] += a2 * bv.z; acc[32 + q*4 + 3] += a2 * bv.w;
                acc[48 + q*4 + 0] += a3 * bv.x; acc[48 + q*4 + 1] += a3 * bv.y;
                acc[48 + q*4 + 2] += a3 * bv.z; acc[48 + q*4 + 3] += a3 * bv.w;
            }
        }
    }
    #pragma unroll
    for (int i = 0; i < 4; i++) {
        #pragma unroll
        for (int q = 0; q < 4; q++) {
            float4 o;
            o.x = fast_tanh(acc[i*16 + q*4 + 0]);
            o.y = fast_tanh(acc[i*16 + q*4 + 1]);
            o.z = fast_tanh(acc[i*16 + q*4 + 2]);
            o.w = fast_tanh(acc[i*16 + q*4 + 3]);
            *(float4*)(comp + (tm*4 + i) * P_ + q * 128 + tn * 4) = o;
        }
    }

    // ---- stages 2/3: hidden layers, K = 512, A = comp (SMEM-resident) ----
    for (int layer = 0; layer < 2; layer++) {
        const float* W = hid + (size_t)layer * P_ * P_;
        #pragma unroll
        for (int a = 0; a < 64; a++) acc[a] = 0.f;

        for (int k0 = 0; k0 < P_; k0 += BK) {
            __syncthreads();                       // protects Ws overwrite + comp visibility
            load_w_chunk(Ws, W + (size_t)k0 * P_, tid);
            __syncthreads();
            #pragma unroll
            for (int k = 0; k < BK; k++) {
                int kk = k0 + k;
                float a0 = comp[(tm*4 + 0) * P_ + kk];
                float a1 = comp[(tm*4 + 1) * P_ + kk];
                float a2 = comp[(tm*4 + 2) * P_ + kk];
                float a3 = comp[(tm*4 + 3) * P_ + kk];
                const float* wr = Ws + k * P_ + tn * 4;
                #pragma unroll
                for (int q = 0; q < 4; q++) {
                    float4 bv = *(const float4*)(wr + q * 128);
                    acc[ 0 + q*4 + 0] += a0 * bv.x; acc[ 0 + q*4 + 1] += a0 * bv.y;
                    acc[ 0 + q*4 + 2] += a0 * bv.z; acc[ 0 + q*4 + 3] += a0 * bv.w;
                    acc[16 + q*4 + 0] += a1 * bv.x; acc[16 + q*4 + 1] += a1 * bv.y;
                    acc[16 + q*4 + 2] += a1 * bv.z; acc[16 + q*4 + 3] += a1 * bv.w;
                    acc[32 + q*4 + 0] += a2 * bv.x; acc[32 + q*4 + 1] += a2 * bv.y;
                    acc[32 + q*4 + 2] += a2 * bv.z; acc[32 + q*4 + 3] += a2 * bv.w;
                    acc[48 + q*4 + 0] += a3 * bv.x; acc[48 + q*4 + 1] += a3 * bv.y;
                    acc[48 + q*4 + 2] += a3 * bv.z; acc[48 + q*4 + 3] += a3 * bv.w;
                }
            }
        }
        __syncthreads();      // all comp reads done before overwrite
        #pragma unroll
        for (int i = 0; i < 4; i++) {
            #pragma unroll
            for (int q = 0; q < 4; q++) {
                float4 o;
                o.x = fast_tanh(acc[i*16 + q*4 + 0]);
                o.y = fast_tanh(acc[i*16 + q*4 + 1]);
                o.z = fast_tanh(acc[i*16 + q*4 + 2]);
                o.w = fast_tanh(acc[i*16 + q*4 + 3]);
                *(float4*)(comp + (tm*4 + i) * P_ + q * 128 + tn * 4) = o;
            }
        }
    }

    // ---- score: g_scores[r] = comp[r] · scorer ----
    __syncthreads();
    if (tid < 128) ((float4*)Ws)[tid] = ((const float4*)scorer)[tid];
    __syncthreads();
    #pragma unroll
    for (int i = 0; i < 4; i++) {
        int m = tm * 4 + i;
        float v = 0.f;
        #pragma unroll
        for (int q = 0; q < 16; q++) {
            int n = tn + q * 32;
            v += comp[m * P_ + n] * Ws[n];
        }
        #pragma unroll
        for (int o = 16; o > 0; o >>= 1)
            v += __shfl_xor_sync(0xffffffffu, v, o);
        if (tn == 0)
            g_scores[R0 + m] = v;
    }
}

// ---------------------------------------------------------------------------
// Kernel 3: masked softmax over s per batch. Mask dtype chosen via g_mask_mode.
// ---------------------------------------------------------------------------
__global__ void __launch_bounds__(256) softmax_kernel(
    const void* __restrict__ mask_raw,
    float* __restrict__ out)                  // [B][SH]
{
    __shared__ float red[256];
    const int b = blockIdx.x;
    const int s = threadIdx.x;
    const int mode = g_mask_mode;
    float e = 0.f;
    if (s < SH) {
        bool m;
        int idx = b * S_ + s;
        if (mode == 0)       m = ((const int*)mask_raw)[idx] != 0;
        else if (mode == 1)  m = ((const float*)mask_raw)[idx] != 0.f;
        else                 m = ((const unsigned char*)mask_raw)[idx] != 0;
        float sc = g_scores[b * SH + s];
        e = m ? expf(sc) : 0.f;
    }
    red[s] = e;
    __syncthreads();
    #pragma unroll
    for (int o = 128; o > 0; o >>= 1) {
        if (s < o) red[s] += red[s + o];
        __syncthreads();
    }
    float inv = 1.f / (red[0] + EPS_);
    if (s < SH)
        out[b * SH + s] = e * inv;
}

// ---------------------------------------------------------------------------
extern "C" void kernel_launch(void* const* d_in, const int* in_sizes, int n_in,
                              void* d_out, int out_size)
{
    // Resolve inputs by element count (robust to metadata ordering).
    int xi = -1, si = -1, mi = -1;
    int q[4] = {-1, -1, -1, -1};
    int nq = 0;
    for (int i = 0; i < n_in; i++) {
        long long sz = in_sizes[i];
        if (sz == (long long)B_ * S_ * D_)      xi = i;
        else if (sz == P_)                      si = i;
        else if (sz == (long long)B_ * S_)      mi = i;
        else if (sz == (long long)D_ * P_ && nq < 4) q[nq++] = i;
    }
    // Fallback to positional if resolution failed
    if (xi < 0 || si < 0 || mi < 0 || nq != 4) {
        xi = 0; q[0] = 1; q[1] = 2; q[2] = 3; q[3] = 4; si = 5; mi = 6;
    }

    const float *w_head, *w_prep, *w_child, *hid;
    if (xi == 0) {
        // insertion order: proj_head, proj_prep, proj_child, hidden_layers
        w_head = (const float*)d_in[q[0]];
        w_prep = (const float*)d_in[q[1]];
        w_child = (const float*)d_in[q[2]];
        hid    = (const float*)d_in[q[3]];
    } else {
        // alphabetical order: hidden_layers, proj_child, proj_head, proj_prep
        hid    = (const float*)d_in[q[0]];
        w_child = (const float*)d_in[q[1]];
        w_head = (const float*)d_in[q[2]];
        w_prep = (const float*)d_in[q[3]];
    }
    const float* x = (const float*)d_in[xi];
    const float* scorer = (const float*)d_in[si];
    const void* mask = d_in[mi];
    float* out = (float*)d_out;

    cudaFuncSetAttribute(main_kernel,
                         cudaFuncAttributeMaxDynamicSharedMemorySize,
                         MAIN_SMEM_BYTES);

    mask_probe_kernel<<<1, 256>>>((const unsigned int*)mask);
    bias_kernel<<<dim3(P_/128, B_/4), 128>>>(x, w_prep, w_child);
    main_kernel<<<NROWS / TM, 256, MAIN_SMEM_BYTES>>>(x, w_head, hid, scorer);
    softmax_kernel<<<B_, 256>>>(mask, out);
}

// round 5
// speedup vs baseline: 4.3055x; 4.3055x over previous
#include <cuda_runtime.h>
#include <cstdint>
#include <cstddef>

// Problem constants
#define B_   256
#define S_   256
#define D_   1024
#define P_   512
#define SH   254
#define NROWS (B_*SH)       // 65024
#define EPS_ 1e-7f

// Scratch (__device__ globals: allocation-free rule)
__device__ float g_bias[B_*P_];
__device__ float g_spart[4*NROWS];                    // per-N-block score partials
__device__ int   g_mask_mode;
__device__ __align__(1024) float g_w1t[(size_t)P_*D_];   // proj_head^T [512][1024] (tf32-rounded)
__device__ __align__(1024) float g_h0t[(size_t)P_*P_];   // hidden0^T  [512][512]
__device__ __align__(1024) float g_h1t[(size_t)P_*P_];   // hidden1^T  [512][512]
__device__ __align__(1024) float g_c0[(size_t)NROWS*P_]; // activations after stage 1
__device__ __align__(1024) float g_c1[(size_t)NROWS*P_]; // activations after stage 2

__device__ __forceinline__ float fast_tanh(float x) {
    float y; asm("tanh.approx.f32 %0, %1;" : "=f"(y) : "f"(x)); return y;
}
__device__ __forceinline__ uint32_t smem_u32(const void* p) {
    uint32_t a;
    asm("{ .reg .u64 t; cvta.to.shared.u64 t, %1; cvt.u32.u64 %0, t; }" : "=r"(a) : "l"(p));
    return a;
}
__device__ __forceinline__ uint32_t tf32_rna(uint32_t u) {
    uint32_t r; float f = __uint_as_float(u);
    asm("cvt.rna.tf32.f32 %0, %1;" : "=r"(r) : "f"(f));
    return r;
}

// ---------------------------------------------------------------------------
// mask dtype probe (reads only first 65536 bytes; deterministic)
// ---------------------------------------------------------------------------
__global__ void __launch_bounds__(256) mask_probe_kernel(const unsigned int* __restrict__ m)
{
    __shared__ int s01, sf;
    if (threadIdx.x == 0) { s01 = 1; sf = 1; }
    __syncthreads();
    bool ok01 = true, okf = true;
    #pragma unroll 4
    for (int it = 0; it < 64; it++) {
        unsigned int v = m[threadIdx.x + it * 256];
        if (v > 1u) ok01 = false;
        if (v != 0u && v != 0x3F800000u) okf = false;
    }
    if (!ok01) atomicAnd(&s01, 0);
    if (!okf)  atomicAnd(&sf, 0);
    __syncthreads();
    if (threadIdx.x == 0) g_mask_mode = s01 ? 0 : (sf ? 1 : 2);
}

// ---------------------------------------------------------------------------
// weight transpose W[K][N] -> Wt[N][K], rounded to tf32 (rna)
// ---------------------------------------------------------------------------
__global__ void __launch_bounds__(256) transpose_rna(
    const float* __restrict__ src, float* __restrict__ dst, int K, int N)
{
    __shared__ float t[32][33];
    int k0 = blockIdx.y * 32, n0 = blockIdx.x * 32;
    int tx = threadIdx.x, ty = threadIdx.y;      // 32 x 8
    #pragma unroll
    for (int i = 0; i < 32; i += 8)
        t[ty + i][tx] = src[(size_t)(k0 + ty + i) * N + n0 + tx];
    __syncthreads();
    #pragma unroll
    for (int i = 0; i < 32; i += 8) {
        float v = t[tx][ty + i];
        asm("cvt.rna.tf32.f32 %0, %1;" : "=f"(v) : "f"(v));
        dst[(size_t)(n0 + ty + i) * K + k0 + tx] = v;
    }
}

// ---------------------------------------------------------------------------
// bias kernel: bias[b][p] = prep·proj_prep[:,p] + child·proj_child[:,p] (fp32)
// ---------------------------------------------------------------------------
__global__ void __launch_bounds__(128) bias_kernel(
    const float* __restrict__ x,
    const float* __restrict__ wp,
    const float* __restrict__ wc)
{
    __shared__ float sP[4][D_];
    __shared__ float sC[4][D_];
    const int tid = threadIdx.x;
    const int b0  = blockIdx.y * 4;
    #pragma unroll
    for (int it = 0; it < 16; it++) {
        int idx  = tid + it * 128;
        int row  = idx >> 8;
        int col4 = idx & 255;
        int bb   = b0 + (row >> 1);
        int which = row & 1;
        const float* src = x + ((size_t)bb * S_ + (S_ - 2) + which) * D_;
        float4 v = *(const float4*)(src + col4 * 4);
        float* dst = which ? &sC[row >> 1][0] : &sP[row >> 1][0];
        *(float4*)(dst + col4 * 4) = v;
    }
    __syncthreads();
    const int p = blockIdx.x * 128 + tid;
    float acc[4] = {0.f, 0.f, 0.f, 0.f};
    #pragma unroll 4
    for (int d = 0; d < D_; d++) {
        float a = wp[(size_t)d * P_ + p];
        float c = wc[(size_t)d * P_ + p];
        #pragma unroll
        for (int j = 0; j < 4; j++) acc[j] += sP[j][d] * a + sC[j][d] * c;
    }
    #pragma unroll
    for (int j = 0; j < 4; j++)
        g_bias[(size_t)(b0 + j) * P_ + p] = acc[j];
}

// ---------------------------------------------------------------------------
// tf32 mma.sync GEMM stage. CTA tile 128x128, BK=32, 2-stage cp.async pipeline.
// 8 warps (2 M x 4 N), warp tile 64x32, mma m16n8k8.
// A rows: EPI==0 -> gather from x (b,s map); else dense [NROWS][K].
// B = transposed weights [512][K] (tf32-rounded).
// EPI: 0 = +bias,tanh -> Cout ; 1 = tanh -> Cout ; 2 = tanh + scorer partial dot
// smem: stage s at s*32768: A[128][32] then B[128][32], fp32, XOR-swizzled 16B chunks.
// ---------------------------------------------------------------------------
#define GSMEM 65536

template<int K, int EPI>
__global__ void __launch_bounds__(256) gemm_tf32(
    const float* __restrict__ A,
    const float* __restrict__ BT,
    const float* __restrict__ scorer,
    float* __restrict__ Cout)
{
    constexpr int T = K / 32;
    extern __shared__ __align__(1024) char smem[];
    const uint32_t sb = smem_u32(smem);
    const int tid = threadIdx.x, lane = tid & 31, wid = tid >> 5;
    const int wm = wid >> 2, wn = wid & 3;
    const int R0 = blockIdx.x * 128, N0 = blockIdx.y * 128;

    // ---- cp.async precomputed offsets (4 A chunks + 4 B chunks per thread) ----
    uint32_t asrcOff[4], bsrcOff[4], sdst[4];
    #pragma unroll
    for (int i = 0; i < 4; i++) {
        int ch = tid + i * 256;           // 0..1023
        int row = ch >> 3;                // 0..127
        int c   = ch & 7;                 // 16B chunk in 128B row
        sdst[i] = (uint32_t)(row * 128 + ((c ^ (row & 7)) << 4));
        int r = R0 + row;
        if (EPI == 0) {
            int b = r / SH; int s2 = r - b * SH;
            asrcOff[i] = (uint32_t)(((b * S_ + s2) * D_ + c * 4) * 4);
        } else {
            asrcOff[i] = (uint32_t)((r * K + c * 4) * 4);
        }
        bsrcOff[i] = (uint32_t)(((N0 + row) * K + c * 4) * 4);
    }
    const char* Ab = (const char*)A;
    const char* Bb = (const char*)BT;

    auto fill = [&](int s, int kt) {
        uint32_t ab = sb + s * 32768;
        uint32_t koff = (uint32_t)kt * 128;   // 32 floats
        #pragma unroll
        for (int i = 0; i < 4; i++) {
            asm volatile("cp.async.cg.shared.global [%0], [%1], 16;"
                :: "r"(ab + sdst[i]), "l"(Ab + asrcOff[i] + koff) : "memory");
            asm volatile("cp.async.cg.shared.global [%0], [%1], 16;"
                :: "r"(ab + 16384 + sdst[i]), "l"(Bb + bsrcOff[i] + koff) : "memory");
        }
        asm volatile("cp.async.commit_group;" ::: "memory");
    };

    float acc[4][4][4];
    #pragma unroll
    for (int a = 0; a < 4; a++)
        #pragma unroll
        for (int b = 0; b < 4; b++)
            #pragma unroll
            for (int c = 0; c < 4; c++) acc[a][b][c] = 0.f;

    fill(0, 0);
    fill(1, 1);
    asm volatile("cp.async.wait_group 1;" ::: "memory");
    __syncthreads();

    // ldmatrix per-thread invariants
    const int aswz = lane & 7;
    const int arow = (lane & 7) + ((lane >> 3) & 1) * 8;   // A: mat order rows, rows, cols, cols
    const int ach  = (lane >> 4) & 1;
    const int brow = (lane & 7) + ((lane >> 4) & 1) * 8;   // B: rows n0-7 c0, c1, n8-15 c0, c1
    const int bch  = (lane >> 3) & 1;

    for (int t = 0; t < T; t++) {
        const int s = t & 1;
        const uint32_t ab = sb + s * 32768;
        const uint32_t bb = ab + 16384;
        #pragma unroll
        for (int kk = 0; kk < 4; kk++) {
            uint32_t ar[4][4], br[2][4];
            #pragma unroll
            for (int mi = 0; mi < 4; mi++) {
                uint32_t addr = ab + (uint32_t)((wm * 64 + mi * 16 + arow) * 128)
                              + (uint32_t)((((kk * 2 + ach) ^ aswz)) << 4);
                asm volatile("ldmatrix.sync.aligned.m8n8.x4.shared.b16 {%0,%1,%2,%3}, [%4];"
                    : "=r"(ar[mi][0]), "=r"(ar[mi][1]), "=r"(ar[mi][2]), "=r"(ar[mi][3])
                    : "r"(addr));
            }
            #pragma unroll
            for (int np = 0; np < 2; np++) {
                uint32_t addr = bb + (uint32_t)((wn * 32 + np * 16 + brow) * 128)
                              + (uint32_t)((((kk * 2 + bch) ^ aswz)) << 4);
                asm volatile("ldmatrix.sync.aligned.m8n8.x4.shared.b16 {%0,%1,%2,%3}, [%4];"
                    : "=r"(br[np][0]), "=r"(br[np][1]), "=r"(br[np][2]), "=r"(br[np][3])
                    : "r"(addr));
            }
            // round A to tf32 (weights pre-rounded at transpose)
            #pragma unroll
            for (int mi = 0; mi < 4; mi++)
                #pragma unroll
                for (int j = 0; j < 4; j++) ar[mi][j] = tf32_rna(ar[mi][j]);
            #pragma unroll
            for (int mi = 0; mi < 4; mi++)
                #pragma unroll
                for (int nj = 0; nj < 4; nj++) {
                    uint32_t b0 = br[nj >> 1][(nj & 1) * 2];
                    uint32_t b1 = br[nj >> 1][(nj & 1) * 2 + 1];
                    asm volatile(
                        "mma.sync.aligned.m16n8k8.row.col.f32.tf32.tf32.f32 "
                        "{%0,%1,%2,%3}, {%4,%5,%6,%7}, {%8,%9}, {%0,%1,%2,%3};"
                        : "+f"(acc[mi][nj][0]), "+f"(acc[mi][nj][1]),
                          "+f"(acc[mi][nj][2]), "+f"(acc[mi][nj][3])
                        : "r"(ar[mi][0]), "r"(ar[mi][1]), "r"(ar[mi][2]), "r"(ar[mi][3]),
                          "r"(b0), "r"(b1));
                }
        }
        __syncthreads();
        if (t + 2 < T) fill(s, t + 2);
        if (t + 1 < T) {
            if (t + 2 < T) asm volatile("cp.async.wait_group 1;" ::: "memory");
            else           asm volatile("cp.async.wait_group 0;" ::: "memory");
            __syncthreads();
        }
    }

    // ---- epilogue ----
    const int r4 = lane >> 2, l2 = (lane & 3) * 2;
    if (EPI < 2) {
        #pragma unroll
        for (int mi = 0; mi < 4; mi++)
            #pragma unroll
            for (int h = 0; h < 2; h++) {
                int m = R0 + wm * 64 + mi * 16 + r4 + h * 8;
                const float* brow_ = g_bias + (size_t)(m / SH) * P_;
                #pragma unroll
                for (int nj = 0; nj < 4; nj++) {
                    int n = N0 + wn * 32 + nj * 8 + l2;
                    float v0 = acc[mi][nj][h * 2 + 0];
                    float v1 = acc[mi][nj][h * 2 + 1];
                    if (EPI == 0) {
                        float2 bv = *(const float2*)(brow_ + n);
                        v0 += bv.x; v1 += bv.y;
                    }
                    float2 o;
                    o.x = fast_tanh(v0);
                    o.y = fast_tanh(v1);
                    *(float2*)(Cout + (size_t)m * P_ + n) = o;
                }
            }
    } else {
        __syncthreads();                    // smem reuse for reduction
        float* red = (float*)smem;          // [4][128]
        #pragma unroll
        for (int mi = 0; mi < 4; mi++)
            #pragma unroll
            for (int h = 0; h < 2; h++) {
                float sum = 0.f;
                #pragma unroll
                for (int nj = 0; nj < 4; nj++) {
                    int n = N0 + wn * 32 + nj * 8 + l2;
                    float v0 = fast_tanh(acc[mi][nj][h * 2 + 0]);
                    float v1 = fast_tanh(acc[mi][nj][h * 2 + 1]);
                    sum += v0 * __ldg(scorer + n) + v1 * __ldg(scorer + n + 1);
                }
                sum += __shfl_xor_sync(0xffffffffu, sum, 1);
                sum += __shfl_xor_sync(0xffffffffu, sum, 2);
                if ((lane & 3) == 0)
                    red[wn * 128 + wm * 64 + mi * 16 + r4 + h * 8] = sum;
            }
        __syncthreads();
        if (tid < 128) {
            float tot = red[tid] + red[128 + tid] + red[256 + tid] + red[384 + tid];
            g_spart[(size_t)blockIdx.y * NROWS + R0 + tid] = tot;
        }
    }
}

// ---------------------------------------------------------------------------
// masked softmax over s per batch; sums the 4 N-block score partials.
// ---------------------------------------------------------------------------
__global__ void __launch_bounds__(256) softmax_kernel(
    const void* __restrict__ mask_raw, float* __restrict__ out)
{
    __shared__ float red[256];
    const int b = blockIdx.x;
    const int s = threadIdx.x;
    const int mode = g_mask_mode;
    float e = 0.f;
    if (s < SH) {
        bool m;
        int idx = b * S_ + s;
        if (mode == 0)      m = ((const int*)mask_raw)[idx] != 0;
        else if (mode == 1) m = ((const float*)mask_raw)[idx] != 0.f;
        else                m = ((const unsigned char*)mask_raw)[idx] != 0;
        int r = b * SH + s;
        float sc = g_spart[r] + g_spart[NROWS + r] + g_spart[2 * NROWS + r] + g_spart[3 * NROWS + r];
        e = m ? expf(sc) : 0.f;
    }
    red[s] = e;
    __syncthreads();
    #pragma unroll
    for (int o = 128; o > 0; o >>= 1) {
        if (s < o) red[s] += red[s + o];
        __syncthreads();
    }
    float inv = 1.f / (red[0] + EPS_);
    if (s < SH) out[b * SH + s] = e * inv;
}

// ---------------------------------------------------------------------------
extern "C" void kernel_launch(void* const* d_in, const int* in_sizes, int n_in,
                              void* d_out, int out_size)
{
    // Resolve inputs by element count (robust to metadata ordering).
    int xi = -1, si = -1, mi = -1;
    int q[4] = {-1, -1, -1, -1};
    int nq = 0;
    for (int i = 0; i < n_in; i++) {
        long long sz = in_sizes[i];
        if (sz == (long long)B_ * S_ * D_)      xi = i;
        else if (sz == P_)                      si = i;
        else if (sz == (long long)B_ * S_)      mi = i;
        else if (sz == (long long)D_ * P_ && nq < 4) q[nq++] = i;
    }
    if (xi < 0 || si < 0 || mi < 0 || nq != 4) {
        xi = 0; q[0] = 1; q[1] = 2; q[2] = 3; q[3] = 4; si = 5; mi = 6;
    }
    const float *w_head, *w_prep, *w_child, *hid;
    if (xi == 0) {
        w_head = (const float*)d_in[q[0]];
        w_prep = (const float*)d_in[q[1]];
        w_child = (const float*)d_in[q[2]];
        hid    = (const float*)d_in[q[3]];
    } else {
        hid    = (const float*)d_in[q[0]];
        w_child = (const float*)d_in[q[1]];
        w_head = (const float*)d_in[q[2]];
        w_prep = (const float*)d_in[q[3]];
    }
    const float* x = (const float*)d_in[xi];
    const float* scorer = (const float*)d_in[si];
    const void* mask = d_in[mi];
    float* out = (float*)d_out;

    float *w1t_p, *h0t_p, *h1t_p, *c0_p, *c1_p;
    cudaGetSymbolAddress((void**)&w1t_p, g_w1t);
    cudaGetSymbolAddress((void**)&h0t_p, g_h0t);
    cudaGetSymbolAddress((void**)&h1t_p, g_h1t);
    cudaGetSymbolAddress((void**)&c0_p,  g_c0);
    cudaGetSymbolAddress((void**)&c1_p,  g_c1);

    cudaFuncSetAttribute(gemm_tf32<1024,0>, cudaFuncAttributeMaxDynamicSharedMemorySize, GSMEM);
    cudaFuncSetAttribute(gemm_tf32<512,1>,  cudaFuncAttributeMaxDynamicSharedMemorySize, GSMEM);
    cudaFuncSetAttribute(gemm_tf32<512,2>,  cudaFuncAttributeMaxDynamicSharedMemorySize, GSMEM);

    mask_probe_kernel<<<1, 256>>>((const unsigned int*)mask);
    transpose_rna<<<dim3(P_/32, D_/32), dim3(32, 8)>>>(w_head,        w1t_p, D_, P_);
    transpose_rna<<<dim3(P_/32, P_/32), dim3(32, 8)>>>(hid,           h0t_p, P_, P_);
    transpose_rna<<<dim3(P_/32, P_/32), dim3(32, 8)>>>(hid + P_ * P_, h1t_p, P_, P_);
    bias_kernel<<<dim3(P_/128, B_/4), 128>>>(x, w_prep, w_child);

    gemm_tf32<1024,0><<<dim3(NROWS/128, 4), 256, GSMEM>>>(x,    w1t_p, scorer, c0_p);
    gemm_tf32<512,1> <<<dim3(NROWS/128, 4), 256, GSMEM>>>(c0_p, h0t_p, scorer, c1_p);
    gemm_tf32<512,2> <<<dim3(NROWS/128, 4), 256, GSMEM>>>(c1_p, h1t_p, scorer, nullptr);

    softmax_kernel<<<B_, 256>>>(mask, out);
}

// round 6
// speedup vs baseline: 4.3805x; 1.0174x over previous
#include <cuda_runtime.h>
#include <cstdint>
#include <cstddef>

// Problem constants
#define B_   256
#define S_   256
#define D_   1024
#define P_   512
#define SH   254
#define NROWS (B_*SH)       // 65024
#define EPS_ 1e-7f

// Scratch (__device__ globals: allocation-free rule)
__device__ float g_bias[B_*P_];
__device__ float g_spart[4*NROWS];                    // per-N-block score partials
__device__ int   g_mask_mode;
__device__ __align__(1024) float g_w1t[(size_t)P_*D_];   // proj_head^T [512][1024] (tf32-rounded)
__device__ __align__(1024) float g_h0t[(size_t)P_*P_];   // hidden0^T  [512][512]
__device__ __align__(1024) float g_h1t[(size_t)P_*P_];   // hidden1^T  [512][512]
__device__ __align__(1024) float g_c0[(size_t)NROWS*P_]; // activations after stage 1 (tf32-rounded)
__device__ __align__(1024) float g_c1[(size_t)NROWS*P_]; // activations after stage 2 (tf32-rounded)

__device__ __forceinline__ float fast_tanh(float x) {
    float y; asm("tanh.approx.f32 %0, %1;" : "=f"(y) : "f"(x)); return y;
}
__device__ __forceinline__ uint32_t smem_u32(const void* p) {
    uint32_t a;
    asm("{ .reg .u64 t; cvta.to.shared.u64 t, %1; cvt.u32.u64 %0, t; }" : "=r"(a) : "l"(p));
    return a;
}
__device__ __forceinline__ uint32_t tf32_rna(uint32_t u) {
    uint32_t r; float f = __uint_as_float(u);
    asm("cvt.rna.tf32.f32 %0, %1;" : "=r"(r) : "f"(f));
    return r;
}
__device__ __forceinline__ float tf32_rna_f(float f) {
    float r; asm("cvt.rna.tf32.f32 %0, %1;" : "=f"(r) : "f"(f)); return r;
}

// ---------------------------------------------------------------------------
// mask dtype probe (reads only first 65536 bytes; deterministic)
// ---------------------------------------------------------------------------
__global__ void __launch_bounds__(256) mask_probe_kernel(const unsigned int* __restrict__ m)
{
    __shared__ int s01, sf;
    if (threadIdx.x == 0) { s01 = 1; sf = 1; }
    __syncthreads();
    bool ok01 = true, okf = true;
    #pragma unroll 4
    for (int it = 0; it < 64; it++) {
        unsigned int v = m[threadIdx.x + it * 256];
        if (v > 1u) ok01 = false;
        if (v != 0u && v != 0x3F800000u) okf = false;
    }
    if (!ok01) atomicAnd(&s01, 0);
    if (!okf)  atomicAnd(&sf, 0);
    __syncthreads();
    if (threadIdx.x == 0) g_mask_mode = s01 ? 0 : (sf ? 1 : 2);
}

// ---------------------------------------------------------------------------
// One launch: transpose all 3 weight matrices W[K][N] -> Wt[N][K], tf32-rna.
// z=0: proj_head (K=1024)  z=1: hidden0 (K=512)  z=2: hidden1 (K=512)
// ---------------------------------------------------------------------------
__global__ void __launch_bounds__(256) transpose_all(
    const float* __restrict__ w_head, const float* __restrict__ hid)
{
    const int z = blockIdx.z;
    const int K = (z == 0) ? D_ : P_;
    if (blockIdx.y * 32 >= K) return;
    const float* src = (z == 0) ? w_head : (hid + (size_t)(z - 1) * P_ * P_);
    float* dst = (z == 0) ? g_w1t : ((z == 1) ? g_h0t : g_h1t);

    __shared__ float t[32][33];
    int k0 = blockIdx.y * 32, n0 = blockIdx.x * 32;
    int tx = threadIdx.x & 31, ty = threadIdx.x >> 5;   // 32 x 8
    #pragma unroll
    for (int i = 0; i < 32; i += 8)
        t[ty + i][tx] = src[(size_t)(k0 + ty + i) * P_ + n0 + tx];
    __syncthreads();
    #pragma unroll
    for (int i = 0; i < 32; i += 8)
        dst[(size_t)(n0 + ty + i) * K + k0 + tx] = tf32_rna_f(t[tx][ty + i]);
}

// ---------------------------------------------------------------------------
// bias kernel: bias[b][p] = prep·proj_prep[:,p] + child·proj_child[:,p] (fp32)
// ---------------------------------------------------------------------------
__global__ void __launch_bounds__(128) bias_kernel(
    const float* __restrict__ x,
    const float* __restrict__ wp,
    const float* __restrict__ wc)
{
    __shared__ float sP[4][D_];
    __shared__ float sC[4][D_];
    const int tid = threadIdx.x;
    const int b0  = blockIdx.y * 4;
    #pragma unroll
    for (int it = 0; it < 16; it++) {
        int idx  = tid + it * 128;
        int row  = idx >> 8;
        int col4 = idx & 255;
        int bb   = b0 + (row >> 1);
        int which = row & 1;
        const float* src = x + ((size_t)bb * S_ + (S_ - 2) + which) * D_;
        float4 v = *(const float4*)(src + col4 * 4);
        float* dst = which ? &sC[row >> 1][0] : &sP[row >> 1][0];
        *(float4*)(dst + col4 * 4) = v;
    }
    __syncthreads();
    const int p = blockIdx.x * 128 + tid;
    float acc[4] = {0.f, 0.f, 0.f, 0.f};
    #pragma unroll 4
    for (int d = 0; d < D_; d++) {
        float a = wp[(size_t)d * P_ + p];
        float c = wc[(size_t)d * P_ + p];
        #pragma unroll
        for (int j = 0; j < 4; j++) acc[j] += sP[j][d] * a + sC[j][d] * c;
    }
    #pragma unroll
    for (int j = 0; j < 4; j++)
        g_bias[(size_t)(b0 + j) * P_ + p] = acc[j];
}

// ---------------------------------------------------------------------------
// tf32 mma.sync GEMM stage. CTA tile 128x128, BK=32, 3-stage cp.async pipeline.
// grid = (4 N-blocks, NROWS/128 row-blocks): N-replicas of an A tile launch
// adjacently -> A re-reads served from L2 (weights are L2-resident anyway).
// 8 warps (2 M x 4 N), warp tile 64x32, mma m16n8k8.
// EPI: 0 = +bias,tanh,rna -> Cout ; 1 = tanh,rna -> Cout ; 2 = tanh + scorer partial
// A-fragments are tf32-rounded in-register only for EPI==0 (x input);
// stages 2/3 consume pre-rounded activations.
// smem: 3 stages x 32768 B (A[128][32] then B[128][32], XOR-swizzled 16B chunks).
// ---------------------------------------------------------------------------
#define GSMEM 98304

template<int K, int EPI>
__global__ void __launch_bounds__(256, 2) gemm_tf32(
    const float* __restrict__ A,
    const float* __restrict__ BT,
    const float* __restrict__ scorer,
    float* __restrict__ Cout)
{
    constexpr int T = K / 32;
    extern __shared__ __align__(1024) char smem[];
    const uint32_t sb = smem_u32(smem);
    const int tid = threadIdx.x, lane = tid & 31, wid = tid >> 5;
    const int wm = wid >> 2, wn = wid & 3;
    const int N0 = blockIdx.x * 128, R0 = blockIdx.y * 128;

    // ---- cp.async precomputed offsets (4 A chunks + 4 B chunks per thread) ----
    uint32_t asrcOff[4], bsrcOff[4], sdst[4];
    #pragma unroll
    for (int i = 0; i < 4; i++) {
        int ch = tid + i * 256;           // 0..1023
        int row = ch >> 3;                // 0..127
        int c   = ch & 7;                 // 16B chunk in 128B row
        sdst[i] = (uint32_t)(row * 128 + ((c ^ (row & 7)) << 4));
        int r = R0 + row;
        if (EPI == 0) {
            int b = r / SH; int s2 = r - b * SH;
            asrcOff[i] = (uint32_t)(((b * S_ + s2) * D_ + c * 4) * 4);
        } else {
            asrcOff[i] = (uint32_t)((r * K + c * 4) * 4);
        }
        bsrcOff[i] = (uint32_t)(((N0 + row) * K + c * 4) * 4);
    }
    const char* Ab = (const char*)A;
    const char* Bb = (const char*)BT;

    auto fill = [&](int slot, int kt) {
        uint32_t ab = sb + slot * 32768;
        uint32_t koff = (uint32_t)kt * 128;   // 32 floats
        #pragma unroll
        for (int i = 0; i < 4; i++) {
            asm volatile("cp.async.cg.shared.global [%0], [%1], 16;"
                :: "r"(ab + sdst[i]), "l"(Ab + asrcOff[i] + koff) : "memory");
            asm volatile("cp.async.cg.shared.global [%0], [%1], 16;"
                :: "r"(ab + 16384 + sdst[i]), "l"(Bb + bsrcOff[i] + koff) : "memory");
        }
        asm volatile("cp.async.commit_group;" ::: "memory");
    };

    float acc[4][4][4];
    #pragma unroll
    for (int a = 0; a < 4; a++)
        #pragma unroll
        for (int b = 0; b < 4; b++)
            #pragma unroll
            for (int c = 0; c < 4; c++) acc[a][b][c] = 0.f;

    fill(0, 0);
    fill(1, 1);
    fill(2, 2);

    // ldmatrix per-thread invariants
    const int aswz = lane & 7;
    const int arow = (lane & 7) + ((lane >> 3) & 1) * 8;
    const int ach  = (lane >> 4) & 1;
    const int brow = (lane & 7) + ((lane >> 4) & 1) * 8;
    const int bch  = (lane >> 3) & 1;

    for (int t = 0; t < T; t++) {
        // wait for oldest outstanding group (chunk t); pending = min(t+3,T)-t
        int rem = T - 1 - t;
        if (rem >= 2)      asm volatile("cp.async.wait_group 2;" ::: "memory");
        else if (rem == 1) asm volatile("cp.async.wait_group 1;" ::: "memory");
        else               asm volatile("cp.async.wait_group 0;" ::: "memory");
        __syncthreads();

        const int slot = t % 3;
        const uint32_t ab = sb + slot * 32768;
        const uint32_t bb = ab + 16384;
        #pragma unroll
        for (int kk = 0; kk < 4; kk++) {
            uint32_t ar[4][4], br[2][4];
            #pragma unroll
            for (int mi = 0; mi < 4; mi++) {
                uint32_t addr = ab + (uint32_t)((wm * 64 + mi * 16 + arow) * 128)
                              + (uint32_t)((((kk * 2 + ach) ^ aswz)) << 4);
                asm volatile("ldmatrix.sync.aligned.m8n8.x4.shared.b16 {%0,%1,%2,%3}, [%4];"
                    : "=r"(ar[mi][0]), "=r"(ar[mi][1]), "=r"(ar[mi][2]), "=r"(ar[mi][3])
                    : "r"(addr));
            }
            #pragma unroll
            for (int np = 0; np < 2; np++) {
                uint32_t addr = bb + (uint32_t)((wn * 32 + np * 16 + brow) * 128)
                              + (uint32_t)((((kk * 2 + bch) ^ aswz)) << 4);
                asm volatile("ldmatrix.sync.aligned.m8n8.x4.shared.b16 {%0,%1,%2,%3}, [%4];"
                    : "=r"(br[np][0]), "=r"(br[np][1]), "=r"(br[np][2]), "=r"(br[np][3])
                    : "r"(addr));
            }
            if (EPI == 0) {
                #pragma unroll
                for (int mi = 0; mi < 4; mi++)
                    #pragma unroll
                    for (int j = 0; j < 4; j++) ar[mi][j] = tf32_rna(ar[mi][j]);
            }
            #pragma unroll
            for (int mi = 0; mi < 4; mi++)
                #pragma unroll
                for (int nj = 0; nj < 4; nj++) {
                    uint32_t b0 = br[nj >> 1][(nj & 1) * 2];
                    uint32_t b1 = br[nj >> 1][(nj & 1) * 2 + 1];
                    asm volatile(
                        "mma.sync.aligned.m16n8k8.row.col.f32.tf32.tf32.f32 "
                        "{%0,%1,%2,%3}, {%4,%5,%6,%7}, {%8,%9}, {%0,%1,%2,%3};"
                        : "+f"(acc[mi][nj][0]), "+f"(acc[mi][nj][1]),
                          "+f"(acc[mi][nj][2]), "+f"(acc[mi][nj][3])
                        : "r"(ar[mi][0]), "r"(ar[mi][1]), "r"(ar[mi][2]), "r"(ar[mi][3]),
                          "r"(b0), "r"(b1));
                }
        }
        __syncthreads();
        if (t + 3 < T) fill(slot, t + 3);
    }

    // ---- epilogue ----
    const int r4 = lane >> 2, l2 = (lane & 3) * 2;
    if (EPI < 2) {
        #pragma unroll
        for (int mi = 0; mi < 4; mi++)
            #pragma unroll
            for (int h = 0; h < 2; h++) {
                int m = R0 + wm * 64 + mi * 16 + r4 + h * 8;
                const float* brow_ = g_bias + (size_t)(m / SH) * P_;
                #pragma unroll
                for (int nj = 0; nj < 4; nj++) {
                    int n = N0 + wn * 32 + nj * 8 + l2;
                    float v0 = acc[mi][nj][h * 2 + 0];
                    float v1 = acc[mi][nj][h * 2 + 1];
                    if (EPI == 0) {
                        float2 bv = *(const float2*)(brow_ + n);
                        v0 += bv.x; v1 += bv.y;
                    }
                    float2 o;
                    o.x = tf32_rna_f(fast_tanh(v0));
                    o.y = tf32_rna_f(fast_tanh(v1));
                    *(float2*)(Cout + (size_t)m * P_ + n) = o;
                }
            }
    } else {
        __syncthreads();                    // smem reuse for reduction
        float* red = (float*)smem;          // [4][128]
        #pragma unroll
        for (int mi = 0; mi < 4; mi++)
            #pragma unroll
            for (int h = 0; h < 2; h++) {
                float sum = 0.f;
                #pragma unroll
                for (int nj = 0; nj < 4; nj++) {
                    int n = N0 + wn * 32 + nj * 8 + l2;
                    float v0 = fast_tanh(acc[mi][nj][h * 2 + 0]);
                    float v1 = fast_tanh(acc[mi][nj][h * 2 + 1]);
                    sum += v0 * __ldg(scorer + n) + v1 * __ldg(scorer + n + 1);
                }
                sum += __shfl_xor_sync(0xffffffffu, sum, 1);
                sum += __shfl_xor_sync(0xffffffffu, sum, 2);
                if ((lane & 3) == 0)
                    red[wn * 128 + wm * 64 + mi * 16 + r4 + h * 8] = sum;
            }
        __syncthreads();
        if (tid < 128) {
            float tot = red[tid] + red[128 + tid] + red[256 + tid] + red[384 + tid];
            g_spart[(size_t)blockIdx.x * NROWS + R0 + tid] = tot;
        }
    }
}

// ---------------------------------------------------------------------------
// masked softmax over s per batch; sums the 4 N-block score partials.
// ---------------------------------------------------------------------------
__global__ void __launch_bounds__(256) softmax_kernel(
    const void* __restrict__ mask_raw, float* __restrict__ out)
{
    __shared__ float red[256];
    const int b = blockIdx.x;
    const int s = threadIdx.x;
    const int mode = g_mask_mode;
    float e = 0.f;
    if (s < SH) {
        bool m;
        int idx = b * S_ + s;
        if (mode == 0)      m = ((const int*)mask_raw)[idx] != 0;
        else if (mode == 1) m = ((const float*)mask_raw)[idx] != 0.f;
        else                m = ((const unsigned char*)mask_raw)[idx] != 0;
        int r = b * SH + s;
        float sc = g_spart[r] + g_spart[NROWS + r] + g_spart[2 * NROWS + r] + g_spart[3 * NROWS + r];
        e = m ? expf(sc) : 0.f;
    }
    red[s] = e;
    __syncthreads();
    #pragma unroll
    for (int o = 128; o > 0; o >>= 1) {
        if (s < o) red[s] += red[s + o];
        __syncthreads();
    }
    float inv = 1.f / (red[0] + EPS_);
    if (s < SH) out[b * SH + s] = e * inv;
}

// ---------------------------------------------------------------------------
extern "C" void kernel_launch(void* const* d_in, const int* in_sizes, int n_in,
                              void* d_out, int out_size)
{
    // Resolve inputs by element count (robust to metadata ordering).
    int xi = -1, si = -1, mi = -1;
    int q[4] = {-1, -1, -1, -1};
    int nq = 0;
    for (int i = 0; i < n_in; i++) {
        long long sz = in_sizes[i];
        if (sz == (long long)B_ * S_ * D_)      xi = i;
        else if (sz == P_)                      si = i;
        else if (sz == (long long)B_ * S_)      mi = i;
        else if (sz == (long long)D_ * P_ && nq < 4) q[nq++] = i;
    }
    if (xi < 0 || si < 0 || mi < 0 || nq != 4) {
        xi = 0; q[0] = 1; q[1] = 2; q[2] = 3; q[3] = 4; si = 5; mi = 6;
    }
    const float *w_head, *w_prep, *w_child, *hid;
    if (xi == 0) {
        w_head = (const float*)d_in[q[0]];
        w_prep = (const float*)d_in[q[1]];
        w_child = (const float*)d_in[q[2]];
        hid    = (const float*)d_in[q[3]];
    } else {
        hid    = (const float*)d_in[q[0]];
        w_child = (const float*)d_in[q[1]];
        w_head = (const float*)d_in[q[2]];
        w_prep = (const float*)d_in[q[3]];
    }
    const float* x = (const float*)d_in[xi];
    const float* scorer = (const float*)d_in[si];
    const void* mask = d_in[mi];
    float* out = (float*)d_out;

    float *w1t_p, *h0t_p, *h1t_p, *c0_p, *c1_p;
    cudaGetSymbolAddress((void**)&w1t_p, g_w1t);
    cudaGetSymbolAddress((void**)&h0t_p, g_h0t);
    cudaGetSymbolAddress((void**)&h1t_p, g_h1t);
    cudaGetSymbolAddress((void**)&c0_p,  g_c0);
    cudaGetSymbolAddress((void**)&c1_p,  g_c1);

    cudaFuncSetAttribute(gemm_tf32<1024,0>, cudaFuncAttributeMaxDynamicSharedMemorySize, GSMEM);
    cudaFuncSetAttribute(gemm_tf32<512,1>,  cudaFuncAttributeMaxDynamicSharedMemorySize, GSMEM);
    cudaFuncSetAttribute(gemm_tf32<512,2>,  cudaFuncAttributeMaxDynamicSharedMemorySize, GSMEM);

    mask_probe_kernel<<<1, 256>>>((const unsigned int*)mask);
    transpose_all<<<dim3(P_/32, D_/32, 3), 256>>>(w_head, hid);
    bias_kernel<<<dim3(P_/128, B_/4), 128>>>(x, w_prep, w_child);

    gemm_tf32<1024,0><<<dim3(4, NROWS/128), 256, GSMEM>>>(x,    w1t_p, scorer, c0_p);
    gemm_tf32<512,1> <<<dim3(4, NROWS/128), 256, GSMEM>>>(c0_p, h0t_p, scorer, c1_p);
    gemm_tf32<512,2> <<<dim3(4, NROWS/128), 256, GSMEM>>>(c1_p, h1t_p, scorer, nullptr);

    softmax_kernel<<<B_, 256>>>(mask, out);
}